// round 4
// baseline (speedup 1.0000x reference)
#include <cuda_runtime.h>
#include <cstdint>

#define B_  8
#define K_  19
#define C_  512
#define HW_ 16384

#define NSPLIT   16
#define S_CHUNK  1024          // HW_/NSPLIT
#define TILE_S   256           // probs tile (s) staged in smem
#define NT       (S_CHUNK / TILE_S)   // 4 tiles per chunk

// probs scratch: 8*19*16384 floats = 9.96 MB
__device__ float g_probs[B_ * K_ * HW_];
// partial results: [split][b][c][k] = 16 * 77824 floats = 4.98 MB
__device__ float g_part[NSPLIT * B_ * C_ * K_];

// packed fp32x2 FMA (sm_100+; PTX-only)
#define FMA2(acc, a, b) \
    asm("fma.rn.f32x2 %0, %1, %2, %0;" : "+l"(acc) : "l"(a), "l"(b))

__device__ __forceinline__ uint32_t smem_u32(const void* p) {
    uint32_t a;
    asm("{ .reg .u64 t; cvta.to.shared.u64 t, %1; cvt.u32.u64 %0, t; }" : "=r"(a) : "l"(p));
    return a;
}
__device__ __forceinline__ void cpasync16(uint32_t dst, const void* src) {
    asm volatile("cp.async.cg.shared.global [%0], [%1], 16;" :: "r"(dst), "l"(src));
}
#define CP_COMMIT()  asm volatile("cp.async.commit_group;" ::: "memory")
#define CP_WAIT(n)   asm volatile("cp.async.wait_group %0;" :: "n"(n) : "memory")

__device__ __forceinline__ float warpMax(float v) {
    #pragma unroll
    for (int o = 16; o; o >>= 1) v = fmaxf(v, __shfl_xor_sync(0xFFFFFFFFu, v, o));
    return v;
}
__device__ __forceinline__ float warpSum(float v) {
    #pragma unroll
    for (int o = 16; o; o >>= 1) v += __shfl_xor_sync(0xFFFFFFFFu, v, o);
    return v;
}

// ---------------------------------------------------------------------------
// Kernel 1: softmax over HW per (b,k) row. 152 CTAs x 512 threads.
// ---------------------------------------------------------------------------
__global__ __launch_bounds__(512) void softmax_kernel(const float* __restrict__ aux) {
    __shared__ float sh[16];
    const int row = blockIdx.x;
    const float4* x = reinterpret_cast<const float4*>(aux + (size_t)row * HW_);
    float4*       p = reinterpret_cast<float4*>(g_probs + (size_t)row * HW_);
    const int tid = threadIdx.x, lane = tid & 31, w = tid >> 5;

    float4 v[8];
    float m = -3.402823466e38f;
    #pragma unroll
    for (int i = 0; i < 8; i++) {
        v[i] = x[tid + i * 512];
        m = fmaxf(m, fmaxf(fmaxf(v[i].x, v[i].y), fmaxf(v[i].z, v[i].w)));
    }
    m = warpMax(m);
    if (lane == 0) sh[w] = m;
    __syncthreads();
    if (w == 0) {
        float t = (lane < 16) ? sh[lane] : -3.402823466e38f;
        t = warpMax(t);
        if (lane == 0) sh[0] = t;
    }
    __syncthreads();
    m = sh[0];
    __syncthreads();

    float s = 0.0f;
    #pragma unroll
    for (int i = 0; i < 8; i++) {
        v[i].x = __expf(v[i].x - m); v[i].y = __expf(v[i].y - m);
        v[i].z = __expf(v[i].z - m); v[i].w = __expf(v[i].w - m);
        s += (v[i].x + v[i].y) + (v[i].z + v[i].w);
    }
    s = warpSum(s);
    if (lane == 0) sh[w] = s;
    __syncthreads();
    if (w == 0) {
        float t = (lane < 16) ? sh[lane] : 0.0f;
        t = warpSum(t);
        if (lane == 0) sh[0] = t;
    }
    __syncthreads();
    const float inv = 1.0f / sh[0];
    #pragma unroll
    for (int i = 0; i < 8; i++) {
        v[i].x *= inv; v[i].y *= inv; v[i].z *= inv; v[i].w *= inv;
        p[tid + i * 512] = v[i];
    }
}

// ---------------------------------------------------------------------------
// Kernel 2: partial[b,c,k,split] = sum_{s in chunk} probs[b,k,s]*feats[b,c,s]
//
// grid = 8b * 8 c-blocks * 16 splits = 1024 CTAs, 256 threads.
// CTA: (b, 64 c, 1024 s).  Warp w: c = cb*64 + w*8 + c_sub.
// Lane: c_sub = lane>>2, s_sub = lane&3 (16 s per step, f32x2 pairs).
// probs tile [19][256] double-buffered in smem via cp.async; all 8 warps
// share the tile (LDS.128, 4 distinct addrs/warp, broadcast, conflict-free).
// Per warp-step: 1 feats LDG.128 (prefetched) + 19 LDS.128 + 38 FFMA2.
// ---------------------------------------------------------------------------
__global__ __launch_bounds__(256, 3) void gather_kernel(const float* __restrict__ feats) {
    __shared__ float sh[2][K_ * TILE_S];               // 2 * 19456 B

    const int bid   = blockIdx.x;
    const int split = bid & (NSPLIT - 1);
    const int cb    = (bid >> 4) & 7;
    const int b     = bid >> 7;
    const int tid   = threadIdx.x;
    const int w     = tid >> 5, lane = tid & 31;
    const int c_sub = lane >> 2, s_sub = lane & 3;
    const int c     = cb * 64 + w * 8 + c_sub;

    const size_t s_base = (size_t)split * S_CHUNK;
    const float* fbase = feats + ((size_t)b * C_ + c) * HW_ + s_base + s_sub * 4;
    const float* pbase = g_probs + (size_t)(b * K_) * HW_ + s_base;

    // tile loader: 19*256 floats = 1216 float4, 256 threads, 5 waves
    auto load_tile = [&](int t, int buf) {
        const float* src0 = pbase + t * TILE_S;
        uint32_t dst0 = smem_u32(&sh[buf][0]);
        #pragma unroll
        for (int i = 0; i < 5; i++) {
            int f = tid + i * 256;                     // float4 index
            if (f < (K_ * TILE_S) / 4) {
                int k = f >> 6;                        // 64 float4 per probs row
                int j = f & 63;
                cpasync16(dst0 + (uint32_t)f * 16, src0 + (size_t)k * HW_ + j * 4);
            }
        }
    };

    unsigned long long acc[K_];
    #pragma unroll
    for (int k = 0; k < K_; k++) acc[k] = 0ull;

    load_tile(0, 0);
    CP_COMMIT();

    ulonglong2 fcur = *reinterpret_cast<const ulonglong2*>(fbase);

    for (int t = 0; t < NT; ++t) {
        __syncthreads();                               // prior reads of buf[(t+1)&1] done
        if (t + 1 < NT) {
            load_tile(t + 1, (t + 1) & 1);
            CP_COMMIT();
            CP_WAIT(1);                                // tile t complete
        } else {
            CP_WAIT(0);
        }
        __syncthreads();                               // tile t visible to all warps

        const float* shb = sh[t & 1];

        #pragma unroll 4
        for (int i = 0; i < TILE_S / 16; ++i) {
            const int it = t * (TILE_S / 16) + i;
            const int itn = (it + 1 < NT * (TILE_S / 16)) ? it + 1 : it;
            ulonglong2 fnext = *reinterpret_cast<const ulonglong2*>(fbase + itn * 16);
            const float* prow = shb + i * 16 + s_sub * 4;
            #pragma unroll
            for (int k = 0; k < K_; k++) {
                ulonglong2 p = *reinterpret_cast<const ulonglong2*>(prow + k * TILE_S);
                FMA2(acc[k], p.x, fcur.x);
                FMA2(acc[k], p.y, fcur.y);
            }
            fcur = fnext;
        }
    }

    // reduce over s_sub (lanes xor 1,2), write partials (each exactly once)
    const size_t pout = (size_t)split * (B_ * C_ * K_) + ((size_t)b * C_ + c) * K_;
    #pragma unroll
    for (int k = 0; k < K_; k++) {
        float2 v;
        asm("mov.b64 {%0, %1}, %2;" : "=f"(v.x), "=f"(v.y) : "l"(acc[k]));
        float sum = v.x + v.y;
        sum += __shfl_xor_sync(0xFFFFFFFFu, sum, 1);
        sum += __shfl_xor_sync(0xFFFFFFFFu, sum, 2);
        if (s_sub == 0) g_part[pout + k] = sum;
    }
}

// ---------------------------------------------------------------------------
// Kernel 3: out[i] = sum_split g_part[split][i]  (fixed order -> deterministic)
// ---------------------------------------------------------------------------
__global__ __launch_bounds__(256) void reduce_kernel(float* __restrict__ out) {
    const int i = blockIdx.x * 256 + threadIdx.x;
    if (i < B_ * C_ * K_) {
        float s = 0.0f;
        #pragma unroll
        for (int sp = 0; sp < NSPLIT; ++sp)
            s += g_part[(size_t)sp * (B_ * C_ * K_) + i];
        out[i] = s;
    }
}

extern "C" void kernel_launch(void* const* d_in, const int* in_sizes, int n_in,
                              void* d_out, int out_size) {
    const float* feats = (const float*)d_in[0];   // bb_feats [8,512,128,128]
    const float* aux   = (const float*)d_in[1];   // aux_out  [8,19,128,128]
    float* out = (float*)d_out;                   // [8,512,19,1] f32

    softmax_kernel<<<B_ * K_, 512>>>(aux);
    gather_kernel<<<B_ * 8 * NSPLIT, 256>>>(feats);
    reduce_kernel<<<(B_ * C_ * K_ + 255) / 256, 256>>>(out);
}

// round 7
// speedup vs baseline: 2.1272x; 2.1272x over previous
#include <cuda_runtime.h>
#include <cstdint>

#define B_  8
#define K_  19
#define C_  512
#define HW_ 16384

#define NSPLIT   32
#define S_CHUNK  512                   // HW_/NSPLIT
#define TILE_S   256                   // probs tile (s) staged in smem
#define NT       (S_CHUNK / TILE_S)    // 2 tiles per chunk

// probs scratch: 8*19*16384 floats = 9.96 MB
__device__ float g_probs[B_ * K_ * HW_];
// partial results: [split][b][c][k] = 32 * 77824 floats = 9.96 MB
__device__ float g_part[NSPLIT * B_ * C_ * K_];

// packed fp32x2 FMA (sm_100+; PTX-only)
#define FMA2(acc, a, b) \
    asm("fma.rn.f32x2 %0, %1, %2, %0;" : "+l"(acc) : "l"(a), "l"(b))

__device__ __forceinline__ uint32_t smem_u32(const void* p) {
    uint32_t a;
    asm("{ .reg .u64 t; cvta.to.shared.u64 t, %1; cvt.u32.u64 %0, t; }" : "=r"(a) : "l"(p));
    return a;
}
__device__ __forceinline__ void cpasync16(uint32_t dst, const void* src) {
    asm volatile("cp.async.cg.shared.global [%0], [%1], 16;" :: "r"(dst), "l"(src));
}
#define CP_COMMIT()  asm volatile("cp.async.commit_group;" ::: "memory")
#define CP_WAIT(n)   asm volatile("cp.async.wait_group %0;" :: "n"(n) : "memory")

__device__ __forceinline__ float warpMax(float v) {
    #pragma unroll
    for (int o = 16; o; o >>= 1) v = fmaxf(v, __shfl_xor_sync(0xFFFFFFFFu, v, o));
    return v;
}
__device__ __forceinline__ float warpSum(float v) {
    #pragma unroll
    for (int o = 16; o; o >>= 1) v += __shfl_xor_sync(0xFFFFFFFFu, v, o);
    return v;
}

// ---------------------------------------------------------------------------
// Kernel 1: softmax over HW per (b,k) row. 152 CTAs x 512 threads.
// ---------------------------------------------------------------------------
__global__ __launch_bounds__(512) void softmax_kernel(const float* __restrict__ aux) {
    __shared__ float sh[16];
    const int row = blockIdx.x;
    const float4* x = reinterpret_cast<const float4*>(aux + (size_t)row * HW_);
    float4*       p = reinterpret_cast<float4*>(g_probs + (size_t)row * HW_);
    const int tid = threadIdx.x, lane = tid & 31, w = tid >> 5;

    float4 v[8];
    float m = -3.402823466e38f;
    #pragma unroll
    for (int i = 0; i < 8; i++) {
        v[i] = x[tid + i * 512];
        m = fmaxf(m, fmaxf(fmaxf(v[i].x, v[i].y), fmaxf(v[i].z, v[i].w)));
    }
    m = warpMax(m);
    if (lane == 0) sh[w] = m;
    __syncthreads();
    if (w == 0) {
        float t = (lane < 16) ? sh[lane] : -3.402823466e38f;
        t = warpMax(t);
        if (lane == 0) sh[0] = t;
    }
    __syncthreads();
    m = sh[0];
    __syncthreads();

    float s = 0.0f;
    #pragma unroll
    for (int i = 0; i < 8; i++) {
        v[i].x = __expf(v[i].x - m); v[i].y = __expf(v[i].y - m);
        v[i].z = __expf(v[i].z - m); v[i].w = __expf(v[i].w - m);
        s += (v[i].x + v[i].y) + (v[i].z + v[i].w);
    }
    s = warpSum(s);
    if (lane == 0) sh[w] = s;
    __syncthreads();
    if (w == 0) {
        float t = (lane < 16) ? sh[lane] : 0.0f;
        t = warpSum(t);
        if (lane == 0) sh[0] = t;
    }
    __syncthreads();
    const float inv = 1.0f / sh[0];
    #pragma unroll
    for (int i = 0; i < 8; i++) {
        v[i].x *= inv; v[i].y *= inv; v[i].z *= inv; v[i].w *= inv;
        p[tid + i * 512] = v[i];
    }
}

// ---------------------------------------------------------------------------
// Kernel 2: partial[b,c,k,split] = sum_{s in chunk} probs[b,k,s]*feats[b,c,s]
//
// grid = 8b * 4 c-blocks * 32 splits = 1024 CTAs, 256 threads (8 warps).
// CTA: (b, 128 c, 512 s).  Warp w: 16 c = cb*128 + w*8 + c_sub (+0 and +64).
// Lane: c_sub = lane>>2, s_sub = lane&3 (16 s per step, f32x2 pairs).
// probs tile [19][256] double-buffered in smem via cp.async; all 8 warps
// share the tile (LDS.128, 4 distinct 16B addrs/warp, broadcast-friendly).
// Per warp-step: 2 feats LDG.128 + 19 LDS.128 + 76 FFMA2 -> FMA-dominated.
// launch_bounds(256,2): 128 regs, NO spills (acc = 76 regs).
// ---------------------------------------------------------------------------
__global__ __launch_bounds__(256, 2) void gather_kernel(const float* __restrict__ feats) {
    __shared__ float sh[2][K_ * TILE_S];               // 2 * 19456 B

    const int bid   = blockIdx.x;
    const int split = bid & (NSPLIT - 1);
    const int cb    = (bid >> 5) & 3;
    const int b     = bid >> 7;
    const int tid   = threadIdx.x;
    const int w     = tid >> 5, lane = tid & 31;
    const int c_sub = lane >> 2, s_sub = lane & 3;
    const int c     = cb * 128 + w * 8 + c_sub;        // second c: c + 64

    const size_t s_base = (size_t)split * S_CHUNK;
    const float* fbase = feats + ((size_t)b * C_ + c) * HW_ + s_base + s_sub * 4;
    const float* pbase = g_probs + (size_t)(b * K_) * HW_ + s_base;

    // tile loader: 19*256 floats = 1216 float4, 256 threads, 5 waves
    auto load_tile = [&](int t, int buf) {
        const float* src0 = pbase + t * TILE_S;
        uint32_t dst0 = smem_u32(&sh[buf][0]);
        #pragma unroll
        for (int i = 0; i < 5; i++) {
            int f = tid + i * 256;                     // float4 index
            if (f < (K_ * TILE_S) / 4) {
                int k = f >> 6;                        // 64 float4 per probs row
                int j = f & 63;
                cpasync16(dst0 + (uint32_t)f * 16, src0 + (size_t)k * HW_ + j * 4);
            }
        }
    };

    unsigned long long acc[K_][2];
    #pragma unroll
    for (int k = 0; k < K_; k++) { acc[k][0] = 0ull; acc[k][1] = 0ull; }

    load_tile(0, 0);
    CP_COMMIT();

    for (int t = 0; t < NT; ++t) {
        __syncthreads();                               // prior reads of buf[(t+1)&1] done
        if (t + 1 < NT) {
            load_tile(t + 1, (t + 1) & 1);
            CP_COMMIT();
            CP_WAIT(1);                                // tile t complete
        } else {
            CP_WAIT(0);
        }
        __syncthreads();                               // tile t visible to all warps

        const float* shb = sh[t & 1];
        const float* fb  = fbase + t * TILE_S;

        #pragma unroll 2
        for (int i = 0; i < TILE_S / 16; ++i) {
            const ulonglong2 f0 = *reinterpret_cast<const ulonglong2*>(fb + i * 16);
            const ulonglong2 f1 = *reinterpret_cast<const ulonglong2*>(fb + 64 * HW_ + i * 16);
            const float* prow = shb + i * 16 + s_sub * 4;
            #pragma unroll
            for (int k = 0; k < K_; k++) {
                const ulonglong2 p = *reinterpret_cast<const ulonglong2*>(prow + k * TILE_S);
                FMA2(acc[k][0], p.x, f0.x);
                FMA2(acc[k][0], p.y, f0.y);
                FMA2(acc[k][1], p.x, f1.x);
                FMA2(acc[k][1], p.y, f1.y);
            }
        }
    }

    // reduce over s_sub (lanes xor 1,2), write partials (each exactly once)
    const size_t pout = (size_t)split * (B_ * C_ * K_) + ((size_t)b * C_ + c) * K_;
    #pragma unroll
    for (int k = 0; k < K_; k++) {
        #pragma unroll
        for (int cp = 0; cp < 2; cp++) {
            float2 v;
            asm("mov.b64 {%0, %1}, %2;" : "=f"(v.x), "=f"(v.y) : "l"(acc[k][cp]));
            float sum = v.x + v.y;
            sum += __shfl_xor_sync(0xFFFFFFFFu, sum, 1);
            sum += __shfl_xor_sync(0xFFFFFFFFu, sum, 2);
            if (s_sub == 0) g_part[pout + (size_t)cp * 64 * K_ + k] = sum;
        }
    }
}

// ---------------------------------------------------------------------------
// Kernel 3: out[i] = sum_split g_part[split][i]  (fixed order -> deterministic)
// ---------------------------------------------------------------------------
__global__ __launch_bounds__(256) void reduce_kernel(float* __restrict__ out) {
    const int i = blockIdx.x * 256 + threadIdx.x;
    if (i < B_ * C_ * K_) {
        float s = 0.0f;
        #pragma unroll
        for (int sp = 0; sp < NSPLIT; ++sp)
            s += g_part[(size_t)sp * (B_ * C_ * K_) + i];
        out[i] = s;
    }
}

extern "C" void kernel_launch(void* const* d_in, const int* in_sizes, int n_in,
                              void* d_out, int out_size) {
    const float* feats = (const float*)d_in[0];   // bb_feats [8,512,128,128]
    const float* aux   = (const float*)d_in[1];   // aux_out  [8,19,128,128]
    float* out = (float*)d_out;                   // [8,512,19,1] f32

    softmax_kernel<<<B_ * K_, 512>>>(aux);
    gather_kernel<<<B_ * 4 * NSPLIT, 256>>>(feats);
    reduce_kernel<<<(B_ * C_ * K_ + 255) / 256, 256>>>(out);
}

// round 8
// speedup vs baseline: 2.4788x; 1.1653x over previous
#include <cuda_runtime.h>
#include <cstdint>

#define B_  8
#define K_  19
#define C_  512
#define HW_ 16384

#define NSPLIT   8
#define S_CHUNK  2048                  // HW_/NSPLIT
#define TILE_S   256                   // probs tile (s) staged in smem
#define NT       (S_CHUNK / TILE_S)    // 8 tiles per chunk
#define NBUF     3                     // cp.async ring depth

// probs scratch: 8*19*16384 floats = 9.96 MB
__device__ float g_probs[B_ * K_ * HW_];
// partial results: [split][b][c][k] = 8 * 77824 floats = 2.49 MB
__device__ float g_part[NSPLIT * B_ * C_ * K_];

// packed fp32x2 FMA (sm_100+; PTX-only)
#define FMA2(acc, a, b) \
    asm("fma.rn.f32x2 %0, %1, %2, %0;" : "+l"(acc) : "l"(a), "l"(b))

__device__ __forceinline__ uint32_t smem_u32(const void* p) {
    uint32_t a;
    asm("{ .reg .u64 t; cvta.to.shared.u64 t, %1; cvt.u32.u64 %0, t; }" : "=r"(a) : "l"(p));
    return a;
}
__device__ __forceinline__ void cpasync16(uint32_t dst, const void* src) {
    asm volatile("cp.async.cg.shared.global [%0], [%1], 16;" :: "r"(dst), "l"(src));
}
#define CP_COMMIT()  asm volatile("cp.async.commit_group;" ::: "memory")
#define CP_WAIT(n)   asm volatile("cp.async.wait_group %0;" :: "n"(n) : "memory")

__device__ __forceinline__ float warpMax(float v) {
    #pragma unroll
    for (int o = 16; o; o >>= 1) v = fmaxf(v, __shfl_xor_sync(0xFFFFFFFFu, v, o));
    return v;
}
__device__ __forceinline__ float warpSum(float v) {
    #pragma unroll
    for (int o = 16; o; o >>= 1) v += __shfl_xor_sync(0xFFFFFFFFu, v, o);
    return v;
}

// ---------------------------------------------------------------------------
// Kernel 1: softmax over HW per (b,k) row. 152 CTAs x 512 threads.
// ---------------------------------------------------------------------------
__global__ __launch_bounds__(512) void softmax_kernel(const float* __restrict__ aux) {
    __shared__ float sh[16];
    const int row = blockIdx.x;
    const float4* x = reinterpret_cast<const float4*>(aux + (size_t)row * HW_);
    float4*       p = reinterpret_cast<float4*>(g_probs + (size_t)row * HW_);
    const int tid = threadIdx.x, lane = tid & 31, w = tid >> 5;

    float4 v[8];
    float m = -3.402823466e38f;
    #pragma unroll
    for (int i = 0; i < 8; i++) {
        v[i] = x[tid + i * 512];
        m = fmaxf(m, fmaxf(fmaxf(v[i].x, v[i].y), fmaxf(v[i].z, v[i].w)));
    }
    m = warpMax(m);
    if (lane == 0) sh[w] = m;
    __syncthreads();
    if (w == 0) {
        float t = (lane < 16) ? sh[lane] : -3.402823466e38f;
        t = warpMax(t);
        if (lane == 0) sh[0] = t;
    }
    __syncthreads();
    m = sh[0];
    __syncthreads();

    float s = 0.0f;
    #pragma unroll
    for (int i = 0; i < 8; i++) {
        v[i].x = __expf(v[i].x - m); v[i].y = __expf(v[i].y - m);
        v[i].z = __expf(v[i].z - m); v[i].w = __expf(v[i].w - m);
        s += (v[i].x + v[i].y) + (v[i].z + v[i].w);
    }
    s = warpSum(s);
    if (lane == 0) sh[w] = s;
    __syncthreads();
    if (w == 0) {
        float t = (lane < 16) ? sh[lane] : 0.0f;
        t = warpSum(t);
        if (lane == 0) sh[0] = t;
    }
    __syncthreads();
    const float inv = 1.0f / sh[0];
    #pragma unroll
    for (int i = 0; i < 8; i++) {
        v[i].x *= inv; v[i].y *= inv; v[i].z *= inv; v[i].w *= inv;
        p[tid + i * 512] = v[i];
    }
}

// ---------------------------------------------------------------------------
// Kernel 2: partial[b,c,k,split] = sum_{s in chunk} probs[b,k,s]*feats[b,c,s]
//
// grid = 8b * 4 c-blocks * 8 splits = 256 CTAs (one full wave), 256 threads.
// CTA: (b, 128 c, 2048 s) = 8 tiles of 256 s.  Warp w: 16 c (c, c+64).
// Lane: c_sub = lane>>2, s_sub = lane&3 (16 s per step, f32x2 pairs).
// probs tile [19][256] in a 3-deep cp.async ring: tile t+2 in flight while
// computing tile t -> smem fill latency hidden; prologue amortized over 8
// tiles. feats prefetched one 16-s step ahead in registers.
// Per warp-step: 2 feats LDG.128 (prefetched) + 19 LDS.128 + 76 FFMA2.
// ---------------------------------------------------------------------------
__global__ __launch_bounds__(256, 2) void gather_kernel(const float* __restrict__ feats) {
    __shared__ float sh[NBUF][K_ * TILE_S];            // 3 * 19456 B = 58368 B

    const int bid   = blockIdx.x;
    const int split = bid & (NSPLIT - 1);
    const int cb    = (bid >> 3) & 3;
    const int b     = bid >> 5;
    const int tid   = threadIdx.x;
    const int w     = tid >> 5, lane = tid & 31;
    const int c_sub = lane >> 2, s_sub = lane & 3;
    const int c     = cb * 128 + w * 8 + c_sub;        // second c: c + 64

    const size_t s_base = (size_t)split * S_CHUNK;
    const float* fbase = feats + ((size_t)b * C_ + c) * HW_ + s_base + s_sub * 4;
    const float* pbase = g_probs + (size_t)(b * K_) * HW_ + s_base;

    // tile loader: 19*256 floats = 1216 float4, 256 threads, 5 waves
    auto load_tile = [&](int t, int buf) {
        const float* src0 = pbase + t * TILE_S;
        uint32_t dst0 = smem_u32(&sh[buf][0]);
        #pragma unroll
        for (int i = 0; i < 5; i++) {
            int f = tid + i * 256;                     // float4 index
            if (f < (K_ * TILE_S) / 4) {
                int k = f >> 6;                        // 64 float4 per probs row
                int j = f & 63;
                cpasync16(dst0 + (uint32_t)f * 16, src0 + (size_t)k * HW_ + j * 4);
            }
        }
    };

    unsigned long long acc[K_][2];
    #pragma unroll
    for (int k = 0; k < K_; k++) { acc[k][0] = 0ull; acc[k][1] = 0ull; }

    // prologue: 2 tiles in flight
    load_tile(0, 0);
    CP_COMMIT();
    load_tile(1, 1);
    CP_COMMIT();

    // feats prefetch (step 0)
    ulonglong2 f0c = *reinterpret_cast<const ulonglong2*>(fbase);
    ulonglong2 f1c = *reinterpret_cast<const ulonglong2*>(fbase + 64 * HW_);

    for (int t = 0; t < NT; ++t) {
        __syncthreads();                   // readers of buf[(t+2)%NBUF] (tile t-1) done
        if (t + 2 < NT) {
            load_tile(t + 2, (t + 2) % NBUF);
            CP_COMMIT();
            CP_WAIT(2);                    // tile t complete (t+1, t+2 may be in flight)
        } else if (t + 1 < NT) {
            CP_WAIT(1);
        } else {
            CP_WAIT(0);
        }
        __syncthreads();                   // tile t visible to all warps

        const float* shb = sh[t % NBUF];

        #pragma unroll 2
        for (int i = 0; i < TILE_S / 16; ++i) {
            const int gi  = t * (TILE_S / 16) + i;
            const int gin = (gi + 1 < NT * (TILE_S / 16)) ? gi + 1 : gi;
            const ulonglong2 f0n = *reinterpret_cast<const ulonglong2*>(fbase + gin * 16);
            const ulonglong2 f1n = *reinterpret_cast<const ulonglong2*>(fbase + 64 * HW_ + gin * 16);
            const float* prow = shb + i * 16 + s_sub * 4;
            #pragma unroll
            for (int k = 0; k < K_; k++) {
                const ulonglong2 p = *reinterpret_cast<const ulonglong2*>(prow + k * TILE_S);
                FMA2(acc[k][0], p.x, f0c.x);
                FMA2(acc[k][0], p.y, f0c.y);
                FMA2(acc[k][1], p.x, f1c.x);
                FMA2(acc[k][1], p.y, f1c.y);
            }
            f0c = f0n;
            f1c = f1n;
        }
    }

    // reduce over s_sub (lanes xor 1,2), write partials (each exactly once)
    const size_t pout = (size_t)split * (B_ * C_ * K_) + ((size_t)b * C_ + c) * K_;
    #pragma unroll
    for (int k = 0; k < K_; k++) {
        #pragma unroll
        for (int cp = 0; cp < 2; cp++) {
            float2 v;
            asm("mov.b64 {%0, %1}, %2;" : "=f"(v.x), "=f"(v.y) : "l"(acc[k][cp]));
            float sum = v.x + v.y;
            sum += __shfl_xor_sync(0xFFFFFFFFu, sum, 1);
            sum += __shfl_xor_sync(0xFFFFFFFFu, sum, 2);
            if (s_sub == 0) g_part[pout + (size_t)cp * 64 * K_ + k] = sum;
        }
    }
}

// ---------------------------------------------------------------------------
// Kernel 3: out[i] = sum_split g_part[split][i]  (fixed order -> deterministic)
// ---------------------------------------------------------------------------
__global__ __launch_bounds__(256) void reduce_kernel(float* __restrict__ out) {
    const int i = blockIdx.x * 256 + threadIdx.x;
    if (i < B_ * C_ * K_) {
        float s = 0.0f;
        #pragma unroll
        for (int sp = 0; sp < NSPLIT; ++sp)
            s += g_part[(size_t)sp * (B_ * C_ * K_) + i];
        out[i] = s;
    }
}

extern "C" void kernel_launch(void* const* d_in, const int* in_sizes, int n_in,
                              void* d_out, int out_size) {
    const float* feats = (const float*)d_in[0];   // bb_feats [8,512,128,128]
    const float* aux   = (const float*)d_in[1];   // aux_out  [8,19,128,128]
    float* out = (float*)d_out;                   // [8,512,19,1] f32

    softmax_kernel<<<B_ * K_, 512>>>(aux);
    gather_kernel<<<B_ * 4 * NSPLIT, 256>>>(feats);
    reduce_kernel<<<(B_ * C_ * K_ + 255) / 256, 256>>>(out);
}